// round 5
// baseline (speedup 1.0000x reference)
#include <cuda_runtime.h>
#include <cstdint>
#include <cstddef>

#define T_STEPS 1024
#define BATCH   64
#define DDIM    128
#define HDIM    512
#define ALPHA   0.1f

#define CLUSTER 8
#define BPC     4
#define NTHR    512

#define ABUF_FLOATS 2560                  // [k(640)][b(4)] ; k<512 fr, k>=512 x
#define SMEM_BYTES  (2 * ABUF_FLOATS * 4) // ping-pong

// ---- packed fp32x2 helpers ----
__device__ __forceinline__ unsigned long long fma2(unsigned long long a,
                                                   unsigned long long b,
                                                   unsigned long long c) {
    unsigned long long d;
    asm("fma.rn.f32x2 %0, %1, %2, %3;" : "=l"(d) : "l"(a), "l"(b), "l"(c));
    return d;
}
__device__ __forceinline__ unsigned long long splat2(float x) {
    unsigned long long d;
    asm("mov.b64 %0, {%1, %1};" : "=l"(d) : "f"(x));
    return d;
}
__device__ __forceinline__ unsigned long long pack2(float lo, float hi) {
    unsigned long long d;
    asm("mov.b64 %0, {%1, %2};" : "=l"(d) : "f"(lo), "f"(hi));
    return d;
}
__device__ __forceinline__ float lo32(unsigned long long v) {
    return __uint_as_float((unsigned)(v & 0xFFFFFFFFull));
}
__device__ __forceinline__ float hi32(unsigned long long v) {
    return __uint_as_float((unsigned)(v >> 32));
}

// ---- cluster helpers ----
__device__ __forceinline__ void st_cluster_v4(unsigned addr, float a, float b,
                                              float c, float d) {
    asm volatile("st.shared::cluster.v4.f32 [%0], {%1, %2, %3, %4};"
                 :: "r"(addr), "f"(a), "f"(b), "f"(c), "f"(d));
}
__device__ __forceinline__ unsigned mapa_u32(unsigned addr, unsigned rank) {
    unsigned d;
    asm("mapa.shared::cluster.u32 %0, %1, %2;" : "=r"(d) : "r"(addr), "r"(rank));
    return d;
}
__device__ __forceinline__ void cluster_arrive_() {
    asm volatile("barrier.cluster.arrive.aligned;" ::: "memory");
}
__device__ __forceinline__ void cluster_wait_() {
    asm volatile("barrier.cluster.wait.aligned;" ::: "memory");
}

__global__ void __launch_bounds__(NTHR, 1)
rnn_kernel(const float* __restrict__ input, const float* __restrict__ Win,
           const float* __restrict__ bin,   const float* __restrict__ Whid,
           const float* __restrict__ bhid,  float* __restrict__ out)
{
    extern __shared__ float sA[];   // [2][640][4]

    const int tid  = threadIdx.x;
    const int lane = tid & 31;
    const int w    = tid >> 5;
    const int bx   = blockIdx.x;
    const int rank = bx & (CLUSTER - 1);
    const int cl   = bx >> 3;
    const int b0   = cl * BPC;
    const int g0   = rank * 64;
    const int gbase = g0 + w * 4;
    const int rank2 = rank * 2;          // own kk chunks: rank2, rank2+1

    // lane's output after the butterfly (same mapping as R4, verified):
    const int vidx = ((lane >> 4) & 1) * 8 + ((lane >> 3) & 1) * 4
                   + ((lane >> 2) & 1) * 2 + ((lane >> 1) & 1);
    const int gl = vidx >> 2;
    const int bb = vidx & 3;
    const int hmine = gbase + gl;

    // ---- W into registers (pre-scaled by ALPHA), g-pair packed ----
    unsigned long long wA[20], wB[20];
    #pragma unroll
    for (int kk = 0; kk < 16; ++kk) {
        int k = kk * 32 + lane;
        wA[kk] = pack2(ALPHA * Whid[(gbase + 0) * HDIM + k],
                       ALPHA * Whid[(gbase + 1) * HDIM + k]);
        wB[kk] = pack2(ALPHA * Whid[(gbase + 2) * HDIM + k],
                       ALPHA * Whid[(gbase + 3) * HDIM + k]);
    }
    #pragma unroll
    for (int kk = 16; kk < 20; ++kk) {
        int k = (kk - 16) * 32 + lane;
        wA[kk] = pack2(ALPHA * Win[(gbase + 0) * DDIM + k],
                       ALPHA * Win[(gbase + 1) * DDIM + k]);
        wB[kk] = pack2(ALPHA * Win[(gbase + 2) * DDIM + k],
                       ALPHA * Win[(gbase + 3) * DDIM + k]);
    }
    const float breg = ALPHA * (bhid[hmine] + bin[hmine]);
    float vreg = 0.0f;

    // ---- buffer 0 init: fr = 0 ; x = input[t=0] ----
    {
        float4 z = {0.f, 0.f, 0.f, 0.f};
        ((float4*)sA)[tid] = z;                 // zeroes fr region of buf0
        int d = w * 8 + (lane >> 2);
        int b = lane & 3;
        sA[(HDIM + d) * 4 + b] = input[(size_t)(b0 + b) * DDIM + d];
    }

    const unsigned aBase = (unsigned)__cvta_generic_to_shared(sA);
    const int xd = w * 8 + (lane >> 2);
    const int xb = lane & 3;

    __syncthreads();
    cluster_arrive_();            // pairs with wait at t=0

    // ---- pre-loop partial GEMM on buffer 0 (own fr slice = 0, plus x) ----
    unsigned long long acc[8];
    #pragma unroll
    for (int i = 0; i < 8; ++i) acc[i] = 0ull;

    #define GEMM_STEP(KIDX, KK)                                               \
        {                                                                      \
            float4 a4 = *(const float4*)&aBuf[(KIDX) * 4];                     \
            unsigned long long s0 = splat2(a4.x), s1 = splat2(a4.y);           \
            unsigned long long s2 = splat2(a4.z), s3 = splat2(a4.w);           \
            acc[0] = fma2(wA[KK], s0, acc[0]); acc[1] = fma2(wB[KK], s0, acc[1]);\
            acc[2] = fma2(wA[KK], s1, acc[2]); acc[3] = fma2(wB[KK], s1, acc[3]);\
            acc[4] = fma2(wA[KK], s2, acc[4]); acc[5] = fma2(wB[KK], s2, acc[5]);\
            acc[6] = fma2(wA[KK], s3, acc[6]); acc[7] = fma2(wB[KK], s3, acc[7]);\
        }

    {
        const float* aBuf = sA;            // buffer 0
        #pragma unroll
        for (int j = 0; j < 2; ++j) {      // own fr slice (zeros at t=0)
            int kk = rank2 + j;
            GEMM_STEP(kk * 32 + lane, kk)
        }
        #pragma unroll
        for (int kk = 16; kk < 20; ++kk)   // x part
            GEMM_STEP(HDIM + (kk - 16) * 32 + lane, kk)
    }

    int cur = 0;
    for (int t = 0; t < T_STEPS; ++t) {
        cluster_wait_();         // peers' fr(t) visible in buffer cur

        // prefetch x(t+1) — latency hidden under the main GEMM
        float xv = 0.f;
        if (t + 1 < T_STEPS)
            xv = input[((size_t)(t + 1) * BATCH + b0 + xb) * DDIM + xd];

        const float* aBuf = sA + cur * ABUF_FLOATS;

        // ---- main GEMM: 14 fr-chunks, skipping own slice ----
        #pragma unroll
        for (int kk = 0; kk < 14; ++kk) {
            int kkm = kk + ((kk >= rank2) ? 2 : 0);
            GEMM_STEP(kkm * 32 + lane, kkm)
        }

        // ---- unpack + warp butterfly (16 outputs over 32 lanes) ----
        float v[16];
        #pragma unroll
        for (int b = 0; b < 4; ++b) {
            v[0 * 4 + b] = lo32(acc[2 * b]);
            v[1 * 4 + b] = hi32(acc[2 * b]);
            v[2 * 4 + b] = lo32(acc[2 * b + 1]);
            v[3 * 4 + b] = hi32(acc[2 * b + 1]);
        }
        #pragma unroll
        for (int s = 16, cnt = 16; s >= 2; s >>= 1, cnt >>= 1) {
            const bool up = (lane & s) != 0;
            const int half = cnt >> 1;
            #pragma unroll
            for (int i = 0; i < 8; ++i) {
                if (i >= half) break;
                float keep = up ? v[i + half] : v[i];
                float send = up ? v[i] : v[i + half];
                float got  = __shfl_xor_sync(0xFFFFFFFFu, send, s);
                v[i] = keep + got;
            }
        }
        v[0] += __shfl_xor_sync(0xFFFFFFFFu, v[0], 1);

        // ---- leaky update + relu ----
        vreg = (1.0f - ALPHA) * vreg + (v[0] + breg);
        float fr = fmaxf(vreg, 0.f);
        if ((lane & 1) == 0)
            out[((size_t)t * BATCH + b0 + bb) * HDIM + hmine] = fr;

        if (t + 1 < T_STEPS) {
            // gather 4 batch values of one g into lanes 0,8,16,24
            float frb1 = __shfl_xor_sync(0xFFFFFFFFu, fr, 2);
            unsigned long long p01 = pack2(fr, frb1);
            unsigned long long p23 = __shfl_xor_sync(0xFFFFFFFFu, p01, 4);

            float* nbuf = sA + (cur ^ 1) * ABUF_FLOATS;
            if ((lane & 7) == 0) {
                float f0 = lo32(p01), f1 = hi32(p01);
                float f2 = lo32(p23), f3 = hi32(p23);
                // local copy (plain smem store)
                *(float4*)&nbuf[hmine * 4] = make_float4(f0, f1, f2, f3);
                // push to the 7 peers
                unsigned boff = (unsigned)(((cur ^ 1) * ABUF_FLOATS
                                            + hmine * 4) * 4);
                #pragma unroll
                for (int c = 0; c < CLUSTER; ++c) {
                    if (c == rank) continue;
                    st_cluster_v4(mapa_u32(aBase, (unsigned)c) + boff,
                                  f0, f1, f2, f3);
                }
            }
            // stage x(t+1) locally
            nbuf[(HDIM + xd) * 4 + xb] = xv;

            cluster_arrive_();       // release pushes; peers may proceed
            __syncthreads();         // own CTA's fr slice + x now readable

            // ---- partial GEMM for step t+1 (own fr slice + x), hides barrier
            #pragma unroll
            for (int i = 0; i < 8; ++i) acc[i] = 0ull;
            {
                const float* pBuf = nbuf;
                #pragma unroll
                for (int j = 0; j < 2; ++j) {
                    int kk = rank2 + j;
                    float4 a4; const float* aBuf = pBuf;
                    GEMM_STEP(kk * 32 + lane, kk)
                    (void)a4;
                }
                const float* aBuf = pBuf;
                #pragma unroll
                for (int kk = 16; kk < 20; ++kk)
                    GEMM_STEP(HDIM + (kk - 16) * 32 + lane, kk)
            }
        }
        cur ^= 1;
    }
}

extern "C" void kernel_launch(void* const* d_in, const int* in_sizes, int n_in,
                              void* d_out, int out_size)
{
    const float* input = (const float*)d_in[0];
    const float* Win   = (const float*)d_in[1];
    const float* bin   = (const float*)d_in[2];
    const float* Whid  = (const float*)d_in[3];
    const float* bhid  = (const float*)d_in[4];
    float* out = (float*)d_out;

    cudaFuncSetAttribute(rnn_kernel,
                         cudaFuncAttributeMaxDynamicSharedMemorySize, SMEM_BYTES);

    cudaLaunchConfig_t cfg = {};
    cfg.gridDim  = dim3(16 * CLUSTER, 1, 1);
    cfg.blockDim = dim3(NTHR, 1, 1);
    cfg.dynamicSmemBytes = SMEM_BYTES;
    cfg.stream = 0;

    cudaLaunchAttribute attr[1];
    attr[0].id = cudaLaunchAttributeClusterDimension;
    attr[0].val.clusterDim.x = CLUSTER;
    attr[0].val.clusterDim.y = 1;
    attr[0].val.clusterDim.z = 1;
    cfg.attrs = attr;
    cfg.numAttrs = 1;

    cudaLaunchKernelEx(&cfg, rnn_kernel, input, Win, bin, Whid, bhid, out);
}

// round 6
// speedup vs baseline: 1.7587x; 1.7587x over previous
#include <cuda_runtime.h>
#include <cstdint>
#include <cstddef>

#define T_STEPS 1024
#define BATCH   64
#define DDIM    128
#define HDIM    512
#define ALPHA   0.1f

#define CLUSTER 8
#define BPC     4
#define NTHR    512

#define ABUF_FLOATS  2560                 // [k(640)][b(4)] ; k<512 fr, k>=512 x
#define STAGE_FLOATS 256                  // 64 g x 4 b, contiguous 1KB
#define SA_FLOATS    (2 * ABUF_FLOATS)    // ping-pong
#define STAGE_OFF    SA_FLOATS
#define MBAR_OFF     (SA_FLOATS + 2 * STAGE_FLOATS)   // float index; 8B aligned
#define SMEM_BYTES   ((MBAR_OFF + 8) * 4)

#define TX_BYTES 8192                     // 8 ranks x 1KB per buffer fill

// ---- packed fp32x2 helpers ----
__device__ __forceinline__ unsigned long long fma2(unsigned long long a,
                                                   unsigned long long b,
                                                   unsigned long long c) {
    unsigned long long d;
    asm("fma.rn.f32x2 %0, %1, %2, %3;" : "=l"(d) : "l"(a), "l"(b), "l"(c));
    return d;
}
__device__ __forceinline__ unsigned long long splat2(float x) {
    unsigned long long d;
    asm("mov.b64 %0, {%1, %1};" : "=l"(d) : "f"(x));
    return d;
}
__device__ __forceinline__ unsigned long long pack2(float lo, float hi) {
    unsigned long long d;
    asm("mov.b64 %0, {%1, %2};" : "=l"(d) : "f"(lo), "f"(hi));
    return d;
}
__device__ __forceinline__ float lo32(unsigned long long v) {
    return __uint_as_float((unsigned)(v & 0xFFFFFFFFull));
}
__device__ __forceinline__ float hi32(unsigned long long v) {
    return __uint_as_float((unsigned)(v >> 32));
}

// ---- cluster / mbarrier helpers ----
__device__ __forceinline__ unsigned mapa_u32(unsigned addr, unsigned rank) {
    unsigned d;
    asm("mapa.shared::cluster.u32 %0, %1, %2;" : "=r"(d) : "r"(addr), "r"(rank));
    return d;
}
__device__ __forceinline__ void mbar_init(unsigned addr, unsigned cnt) {
    asm volatile("mbarrier.init.shared.b64 [%0], %1;" :: "r"(addr), "r"(cnt) : "memory");
}
__device__ __forceinline__ void mbar_arrive_expect_tx(unsigned addr, unsigned bytes) {
    asm volatile("mbarrier.arrive.expect_tx.shared.b64 _, [%0], %1;"
                 :: "r"(addr), "r"(bytes) : "memory");
}
__device__ __forceinline__ void mbar_wait_parity(unsigned addr, unsigned parity) {
    unsigned done;
    asm volatile(
        "{\n\t.reg .pred p;\n\t"
        "mbarrier.try_wait.parity.acquire.cta.shared::cta.b64 p, [%1], %2;\n\t"
        "selp.b32 %0, 1, 0, p;\n\t}"
        : "=r"(done) : "r"(addr), "r"(parity) : "memory");
    if (!done) {
        asm volatile(
            "{\n\t.reg .pred P1;\n\t"
            "WAIT_LOOP_%=:\n\t"
            "mbarrier.try_wait.parity.acquire.cta.shared::cta.b64 P1, [%0], %1, 0x989680;\n\t"
            "@P1 bra.uni WAIT_DONE_%=;\n\t"
            "bra.uni WAIT_LOOP_%=;\n\t"
            "WAIT_DONE_%=:\n\t}"
            :: "r"(addr), "r"(parity) : "memory");
    }
}
__device__ __forceinline__ void bulk_dsmem(unsigned dst_cluster, unsigned src_cta,
                                           unsigned bytes, unsigned mbar_cluster) {
    asm volatile(
        "cp.async.bulk.shared::cluster.shared::cta.mbarrier::complete_tx::bytes "
        "[%0], [%1], %2, [%3];"
        :: "r"(dst_cluster), "r"(src_cta), "r"(bytes), "r"(mbar_cluster) : "memory");
}
__device__ __forceinline__ void fence_proxy_async_cta() {
    asm volatile("fence.proxy.async.shared::cta;" ::: "memory");
}
__device__ __forceinline__ void cluster_sync_() {
    asm volatile("barrier.cluster.arrive.aligned;" ::: "memory");
    asm volatile("barrier.cluster.wait.aligned;" ::: "memory");
}

__global__ void __launch_bounds__(NTHR, 1)
rnn_kernel(const float* __restrict__ input, const float* __restrict__ Win,
           const float* __restrict__ bin,   const float* __restrict__ Whid,
           const float* __restrict__ bhid,  float* __restrict__ out)
{
    extern __shared__ float sA[];   // [2][640][4] | stage[2][256] | mbar[2]

    const int tid  = threadIdx.x;
    const int lane = tid & 31;
    const int w    = tid >> 5;
    const int bx   = blockIdx.x;
    const int rank = bx & (CLUSTER - 1);
    const int cl   = bx >> 3;
    const int b0   = cl * BPC;
    const int g0   = rank * 64;
    const int gbase = g0 + w * 4;

    // lane's output after the butterfly (verified mapping, R4):
    const int vidx = ((lane >> 4) & 1) * 8 + ((lane >> 3) & 1) * 4
                   + ((lane >> 2) & 1) * 2 + ((lane >> 1) & 1);
    const int gl = vidx >> 2;
    const int bb = vidx & 3;
    const int hmine = gbase + gl;

    // ---- W into registers (pre-scaled by ALPHA), g-pair packed; all static idx
    unsigned long long wA[20], wB[20];
    #pragma unroll
    for (int kk = 0; kk < 16; ++kk) {
        int k = kk * 32 + lane;
        wA[kk] = pack2(ALPHA * Whid[(gbase + 0) * HDIM + k],
                       ALPHA * Whid[(gbase + 1) * HDIM + k]);
        wB[kk] = pack2(ALPHA * Whid[(gbase + 2) * HDIM + k],
                       ALPHA * Whid[(gbase + 3) * HDIM + k]);
    }
    #pragma unroll
    for (int kk = 16; kk < 20; ++kk) {
        int k = (kk - 16) * 32 + lane;
        wA[kk] = pack2(ALPHA * Win[(gbase + 0) * DDIM + k],
                       ALPHA * Win[(gbase + 1) * DDIM + k]);
        wB[kk] = pack2(ALPHA * Win[(gbase + 2) * DDIM + k],
                       ALPHA * Win[(gbase + 3) * DDIM + k]);
    }
    const float breg = ALPHA * (bhid[hmine] + bin[hmine]);
    float vreg = 0.0f;

    const unsigned smemBase = (unsigned)__cvta_generic_to_shared(sA);
    const unsigned mbarBase = smemBase + MBAR_OFF * 4;

    // ---- init: buffer0 fr = 0 ; x = input[t=0]; arm both mbarriers ----
    {
        float4 z = {0.f, 0.f, 0.f, 0.f};
        ((float4*)sA)[tid] = z;                 // zeroes fr region of buf0
        int d = w * 8 + (lane >> 2);
        int b = lane & 3;
        sA[(HDIM + d) * 4 + b] = input[(size_t)(b0 + b) * DDIM + d];
    }
    if (tid == 0) {
        mbar_init(mbarBase + 0, 1);
        mbar_init(mbarBase + 8, 1);
        mbar_arrive_expect_tx(mbarBase + 0, TX_BYTES);   // buf0's first comm use (t=2)
        mbar_arrive_expect_tx(mbarBase + 8, TX_BYTES);   // buf1 (t=1)
    }
    __syncthreads();
    cluster_sync_();   // all mbars initialized before any peer bulk-copy lands

    const int xd = w * 8 + (lane >> 2);
    const int xb = lane & 3;

    #define GEMM_STEP(KIDX, KK)                                                \
        {                                                                      \
            float4 a4 = *(const float4*)&aBuf[(KIDX) * 4];                     \
            unsigned long long s0 = splat2(a4.x), s1 = splat2(a4.y);           \
            unsigned long long s2 = splat2(a4.z), s3 = splat2(a4.w);           \
            acc[0] = fma2(wA[KK], s0, acc[0]); acc[1] = fma2(wB[KK], s0, acc[1]);\
            acc[2] = fma2(wA[KK], s1, acc[2]); acc[3] = fma2(wB[KK], s1, acc[3]);\
            acc[4] = fma2(wA[KK], s2, acc[4]); acc[5] = fma2(wB[KK], s2, acc[5]);\
            acc[6] = fma2(wA[KK], s3, acc[6]); acc[7] = fma2(wB[KK], s3, acc[7]);\
        }

    // ---- prologue: x-part of step 0 (fr part is all zeros, skipped) ----
    unsigned long long acc[8];
    #pragma unroll
    for (int i = 0; i < 8; ++i) acc[i] = 0ull;
    {
        const float* aBuf = sA;
        #pragma unroll
        for (int kk = 16; kk < 20; ++kk)
            GEMM_STEP(HDIM + (kk - 16) * 32 + lane, kk)
    }

    int ph0 = 0, ph1 = 0;
    int cur = 0;
    for (int t = 0; t < T_STEPS; ++t) {
        // ---- wait for peers' fr(t) via tx-count; re-arm for t+2 ----
        if (t > 0) {
            unsigned mb = mbarBase + (unsigned)(cur * 8);
            unsigned par = (unsigned)(cur ? ph1 : ph0);
            mbar_wait_parity(mb, par);
            if (cur) ph1 ^= 1; else ph0 ^= 1;
            if (tid == 0) mbar_arrive_expect_tx(mb, TX_BYTES);
        }

        // prefetch x(t+1) — hidden under the main GEMM
        float xv = 0.f;
        if (t + 1 < T_STEPS)
            xv = input[((size_t)(t + 1) * BATCH + b0 + xb) * DDIM + xd];

        const float* aBuf = sA + cur * ABUF_FLOATS;

        // ---- main GEMM: all 16 fr chunks, static indices ----
        #pragma unroll
        for (int kk = 0; kk < 16; ++kk)
            GEMM_STEP(kk * 32 + lane, kk)

        // ---- unpack + warp butterfly (16 outputs over 32 lanes) ----
        float v[16];
        #pragma unroll
        for (int b = 0; b < 4; ++b) {
            v[0 * 4 + b] = lo32(acc[2 * b]);
            v[1 * 4 + b] = hi32(acc[2 * b]);
            v[2 * 4 + b] = lo32(acc[2 * b + 1]);
            v[3 * 4 + b] = hi32(acc[2 * b + 1]);
        }
        #pragma unroll
        for (int s = 16, cnt = 16; s >= 2; s >>= 1, cnt >>= 1) {
            const bool up = (lane & s) != 0;
            const int half = cnt >> 1;
            #pragma unroll
            for (int i = 0; i < 8; ++i) {
                if (i >= half) break;
                float keep = up ? v[i + half] : v[i];
                float send = up ? v[i] : v[i + half];
                float got  = __shfl_xor_sync(0xFFFFFFFFu, send, s);
                v[i] = keep + got;
            }
        }
        v[0] += __shfl_xor_sync(0xFFFFFFFFu, v[0], 1);

        // ---- leaky update + relu ----
        vreg = (1.0f - ALPHA) * vreg + (v[0] + breg);
        float fr = fmaxf(vreg, 0.f);
        if ((lane & 1) == 0)
            out[((size_t)t * BATCH + b0 + bb) * HDIM + hmine] = fr;

        if (t + 1 < T_STEPS) {
            const int nxt = cur ^ 1;
            float* stage = sA + STAGE_OFF + nxt * STAGE_FLOATS;
            float* nbuf  = sA + nxt * ABUF_FLOATS;

            // gather 4 batch values per g into lanes 0,8,16,24; write staging
            float frb1 = __shfl_xor_sync(0xFFFFFFFFu, fr, 2);
            unsigned long long p01 = pack2(fr, frb1);
            unsigned long long p23 = __shfl_xor_sync(0xFFFFFFFFu, p01, 4);
            if ((lane & 7) == 0) {
                int myg = w * 4 + (lane >> 3);   // local g index 0..63
                *(float4*)&stage[myg * 4] =
                    make_float4(lo32(p01), hi32(p01), lo32(p23), hi32(p23));
            }
            // stage x(t+1) locally into next buffer
            nbuf[(HDIM + xd) * 4 + xb] = xv;

            __syncthreads();   // staging + x visible CTA-wide

            if (tid == 0) {
                fence_proxy_async_cta();   // order STS before async-proxy reads
                unsigned src  = smemBase + (unsigned)((STAGE_OFF + nxt * STAGE_FLOATS) * 4);
                unsigned dOff = smemBase + (unsigned)((nxt * ABUF_FLOATS + g0 * 4) * 4);
                unsigned mOff = mbarBase + (unsigned)(nxt * 8);
                #pragma unroll
                for (int c = 0; c < CLUSTER; ++c) {
                    bulk_dsmem(mapa_u32(dOff, (unsigned)c), src, 1024,
                               mapa_u32(mOff, (unsigned)c));
                }
            }

            // ---- pre-wait x-part GEMM for step t+1 (local data, static idx)
            #pragma unroll
            for (int i = 0; i < 8; ++i) acc[i] = 0ull;
            {
                const float* aBuf = nbuf;
                #pragma unroll
                for (int kk = 16; kk < 20; ++kk)
                    GEMM_STEP(HDIM + (kk - 16) * 32 + lane, kk)
            }
        }
        cur ^= 1;
    }
}

extern "C" void kernel_launch(void* const* d_in, const int* in_sizes, int n_in,
                              void* d_out, int out_size)
{
    const float* input = (const float*)d_in[0];
    const float* Win   = (const float*)d_in[1];
    const float* bin   = (const float*)d_in[2];
    const float* Whid  = (const float*)d_in[3];
    const float* bhid  = (const float*)d_in[4];
    float* out = (float*)d_out;

    cudaFuncSetAttribute(rnn_kernel,
                         cudaFuncAttributeMaxDynamicSharedMemorySize, SMEM_BYTES);

    cudaLaunchConfig_t cfg = {};
    cfg.gridDim  = dim3(16 * CLUSTER, 1, 1);
    cfg.blockDim = dim3(NTHR, 1, 1);
    cfg.dynamicSmemBytes = SMEM_BYTES;
    cfg.stream = 0;

    cudaLaunchAttribute attr[1];
    attr[0].id = cudaLaunchAttributeClusterDimension;
    attr[0].val.clusterDim.x = CLUSTER;
    attr[0].val.clusterDim.y = 1;
    attr[0].val.clusterDim.z = 1;
    cfg.attrs = attr;
    cfg.numAttrs = 1;

    cudaLaunchKernelEx(&cfg, rnn_kernel, input, Win, bin, Whid, bhid, out);
}